// round 9
// baseline (speedup 1.0000x reference)
#include <cuda_runtime.h>
#include <cstdint>
#include <math.h>

#define BATCH   8
#define SEQ     2048
#define DMODEL  512
#define ROWS    (BATCH * SEQ)
#define SCALE   0.044194173824159216f

__device__ float g_Q[(size_t)ROWS * DMODEL];
__device__ float g_K[(size_t)ROWS * DMODEL];
__device__ float g_V[(size_t)ROWS * DMODEL];
__device__ float g_Vt[(size_t)BATCH * DMODEL * SEQ];   // [z][v][t]
__device__ float g_Wt[3 * DMODEL * DMODEL];            // [z][n][c]
__device__ float g_S[(size_t)BATCH * SEQ * SEQ];

// ---------------------------------------------------------------------------
__device__ __forceinline__ void mma8(float c[4], const uint32_t a[4],
                                     uint32_t b0, uint32_t b1) {
    asm volatile(
        "mma.sync.aligned.m16n8k8.row.col.f32.tf32.tf32.f32 "
        "{%0,%1,%2,%3}, {%4,%5,%6,%7}, {%8,%9}, {%0,%1,%2,%3};"
        : "+f"(c[0]), "+f"(c[1]), "+f"(c[2]), "+f"(c[3])
        : "r"(a[0]), "r"(a[1]), "r"(a[2]), "r"(a[3]), "r"(b0), "r"(b1));
}
__device__ __forceinline__ void cpa16(uint32_t dst, const float* src) {
    asm volatile("cp.async.cg.shared.global [%0], [%1], 16;"
                 :: "r"(dst), "l"(src) : "memory");
}
__device__ __forceinline__ void cpa_commit() {
    asm volatile("cp.async.commit_group;" ::: "memory");
}

#define TSTRIDE 36
#define TILE_FLOATS (128 * TSTRIDE)                 // 4608 floats = 18432 B
#define STAGE_FLOATS (2 * TILE_FLOATS)              // A + B
#define SMEM_BYTES (3 * STAGE_FLOATS * 4)           // 110592 B, 3 stages

// async tile load: gmem [row][k] (k contiguous) -> smem rows stride 36
__device__ __forceinline__ void load_tile_async(uint32_t smdst, const float* G,
                                                int ld, int r0, int c0) {
    const int t = threadIdx.x, row = t >> 1, kh = (t & 1) * 16;
    const float* src = G + (size_t)(r0 + row) * ld + c0 + kh;
    const uint32_t d = smdst + row * (TSTRIDE * 4) + kh * 4;
#pragma unroll
    for (int i = 0; i < 4; i++) cpa16(d + i * 16, src + i * 4);
}

// C[128,128] = A[128,32*kc] * B[128,32*kc]^T, both k-major. 8 warps (4Mx2N).
// Fragments via direct LDS (PTX m16n8k8 tf32 layout); raw fp32 operands
// (HMMA uses only the tf32 bits -> truncation rounding).
__device__ __forceinline__ void gemm_core(float* sm,
                                          const float* A, int lda, int m0,
                                          const float* B, int ldb, int n0,
                                          int kChunks, float acc[2][8][4]) {
    const uint32_t smb = (uint32_t)__cvta_generic_to_shared(sm);
    const int lane = threadIdx.x & 31, wid = threadIdx.x >> 5;
    const int wm = wid >> 1, wn = wid & 1;
    const int g = lane >> 2, tt = lane & 3;

#pragma unroll
    for (int i = 0; i < 2; i++)
#pragma unroll
        for (int j = 0; j < 8; j++)
#pragma unroll
            for (int k = 0; k < 4; k++) acc[i][j][k] = 0.f;

    // prologue: issue chunks 0 and 1
    load_tile_async(smb, A, lda, m0, 0);
    load_tile_async(smb + TILE_FLOATS * 4, B, ldb, n0, 0);
    cpa_commit();
    if (kChunks > 1) {
        load_tile_async(smb + STAGE_FLOATS * 4, A, lda, m0, 32);
        load_tile_async(smb + STAGE_FLOATS * 4 + TILE_FLOATS * 4, B, ldb, n0, 32);
        cpa_commit();
    }

    for (int c = 0; c < kChunks; c++) {
        if (c + 1 < kChunks)
            asm volatile("cp.async.wait_group 1;" ::: "memory");
        else
            asm volatile("cp.async.wait_group 0;" ::: "memory");
        __syncthreads();   // chunk c visible to all; prior compute done

        if (c + 2 < kChunks) {   // refill stage (c+2)%3 (last read: compute c-1)
            const uint32_t sb = smb + ((c + 2) % 3) * (STAGE_FLOATS * 4);
            load_tile_async(sb, A, lda, m0, (c + 2) * 32);
            load_tile_async(sb + TILE_FLOATS * 4, B, ldb, n0, (c + 2) * 32);
            cpa_commit();
        }

        const float* As = sm + (c % 3) * STAGE_FLOATS;
        const float* Bs = As + TILE_FLOATS;
        const float* Ab = As + (wm * 32 + g) * TSTRIDE + tt;
        const float* Bb = Bs + (wn * 64 + g) * TSTRIDE + tt;
#pragma unroll
        for (int ks = 0; ks < 4; ks++) {
            uint32_t a[2][4];
#pragma unroll
            for (int mi = 0; mi < 2; mi++) {
                const float* p = Ab + mi * (16 * TSTRIDE) + ks * 8;
                a[mi][0] = __float_as_uint(p[0]);
                a[mi][1] = __float_as_uint(p[8 * TSTRIDE]);
                a[mi][2] = __float_as_uint(p[4]);
                a[mi][3] = __float_as_uint(p[8 * TSTRIDE + 4]);
            }
#pragma unroll
            for (int nj = 0; nj < 8; nj++) {
                const float* p = Bb + nj * (8 * TSTRIDE) + ks * 8;
                uint32_t b0 = __float_as_uint(p[0]);
                uint32_t b1 = __float_as_uint(p[4]);
#pragma unroll
                for (int mi = 0; mi < 2; mi++)
                    mma8(acc[mi][nj], a[mi], b0, b1);
            }
        }
    }
}
// acc coords: row = m0+wm*32+mi*16+(lane>>2) [+8 for c2/c3],
//             col = n0+wn*64+ni*8+(lane&3)*2, (c0,c1) adjacent cols.

// ---------------------------------------------------------------------------
__global__ void __launch_bounds__(256) qkv_gemm_tc(
    const float* __restrict__ x,
    const float* __restrict__ b0, const float* __restrict__ b1,
    const float* __restrict__ b2) {
    extern __shared__ float sm[];
    const float* bias; float* C;
    if (blockIdx.z == 0)      { bias = b0; C = g_Q; }
    else if (blockIdx.z == 1) { bias = b1; C = g_K; }
    else                      { bias = b2; C = g_V; }
    const float* W = g_Wt + (size_t)blockIdx.z * DMODEL * DMODEL;
    const int m0 = blockIdx.y * 128, n0 = blockIdx.x * 128;
    float acc[2][8][4];
    gemm_core(sm, x, DMODEL, m0, W, DMODEL, n0, DMODEL / 32, acc);

    const int lane = threadIdx.x & 31, wid = threadIdx.x >> 5;
    const int wm = wid >> 1, wn = wid & 1;
    const int r = lane >> 2, cb = (lane & 3) * 2;
#pragma unroll
    for (int mi = 0; mi < 2; mi++)
#pragma unroll
        for (int ni = 0; ni < 8; ni++) {
            int row = m0 + wm * 32 + mi * 16 + r;
            int col = n0 + wn * 64 + ni * 8 + cb;
            float2 bb = *(const float2*)&bias[col];
            *(float2*)(C + (size_t)row * DMODEL + col) =
                make_float2(acc[mi][ni][0] + bb.x, acc[mi][ni][1] + bb.y);
            *(float2*)(C + (size_t)(row + 8) * DMODEL + col) =
                make_float2(acc[mi][ni][2] + bb.x, acc[mi][ni][3] + bb.y);
        }
}

__global__ void __launch_bounds__(256) s_gemm_tc() {
    if (blockIdx.x > blockIdx.y) return;   // strictly-future tile: skip
    extern __shared__ float sm[];
    const int z = blockIdx.z;
    const int m0 = blockIdx.y * 128, n0 = blockIdx.x * 128;
    const float* Q = g_Q + (size_t)z * SEQ * DMODEL;
    const float* K = g_K + (size_t)z * SEQ * DMODEL;
    float* S = g_S + (size_t)z * SEQ * SEQ;
    float acc[2][8][4];
    gemm_core(sm, Q, DMODEL, m0, K, DMODEL, n0, DMODEL / 32, acc);

    const int lane = threadIdx.x & 31, wid = threadIdx.x >> 5;
    const int wm = wid >> 1, wn = wid & 1;
    const int r = lane >> 2, cb = (lane & 3) * 2;
#pragma unroll
    for (int mi = 0; mi < 2; mi++)
#pragma unroll
        for (int ni = 0; ni < 8; ni++) {
            int row = m0 + wm * 32 + mi * 16 + r;
            int col = n0 + wn * 64 + ni * 8 + cb;
            *(float2*)(S + (size_t)row * SEQ + col) =
                make_float2(acc[mi][ni][0] * SCALE, acc[mi][ni][1] * SCALE);
            *(float2*)(S + (size_t)(row + 8) * SEQ + col) =
                make_float2(acc[mi][ni][2] * SCALE, acc[mi][ni][3] * SCALE);
        }
}

__global__ void __launch_bounds__(256) pv_gemm_tc(float* __restrict__ out) {
    extern __shared__ float sm[];
    const int z = blockIdx.z, qt = blockIdx.y;
    const int m0 = qt * 128, n0 = blockIdx.x * 128;
    const float* P = g_S + (size_t)z * SEQ * SEQ;
    const float* V = g_Vt + (size_t)z * DMODEL * SEQ;   // [v][t], k-major
    float acc[2][8][4];
    gemm_core(sm, P, SEQ, m0, V, SEQ, n0, (qt + 1) * 4, acc);

    const int lane = threadIdx.x & 31, wid = threadIdx.x >> 5;
    const int wm = wid >> 1, wn = wid & 1;
    const int r = lane >> 2, cb = (lane & 3) * 2;
#pragma unroll
    for (int mi = 0; mi < 2; mi++)
#pragma unroll
        for (int ni = 0; ni < 8; ni++) {
            int row = m0 + wm * 32 + mi * 16 + r;
            int col = n0 + wn * 64 + ni * 8 + cb;
            *(float2*)(out + ((size_t)z * SEQ + row) * 1024 + 512 + col) =
                make_float2(acc[mi][ni][0], acc[mi][ni][1]);
            *(float2*)(out + ((size_t)z * SEQ + row + 8) * 1024 + 512 + col) =
                make_float2(acc[mi][ni][2], acc[mi][ni][3]);
        }
}

// ---------------------------------------------------------------------------
// transposes: W [c][n] -> Wt [n][c];  V [t][v] -> Vt [v][t]
// ---------------------------------------------------------------------------
__global__ void __launch_bounds__(256) wt_kernel(
    const float* __restrict__ W0, const float* __restrict__ W1,
    const float* __restrict__ W2) {
    __shared__ float tile[32][33];
    const float* W = blockIdx.z == 0 ? W0 : (blockIdx.z == 1 ? W1 : W2);
    float* Wt = g_Wt + (size_t)blockIdx.z * DMODEL * DMODEL;
    const int n0 = blockIdx.x * 32, c0 = blockIdx.y * 32;
    const int tx = threadIdx.x & 31, ty = threadIdx.x >> 5;
#pragma unroll
    for (int i = 0; i < 32; i += 8)
        tile[ty + i][tx] = W[(size_t)(c0 + ty + i) * DMODEL + n0 + tx];
    __syncthreads();
#pragma unroll
    for (int i = 0; i < 32; i += 8)
        Wt[(size_t)(n0 + ty + i) * DMODEL + c0 + tx] = tile[tx][ty + i];
}

__global__ void __launch_bounds__(256) vt_kernel() {
    __shared__ float tile[32][33];
    const int z = blockIdx.z;
    const float* V = g_V + (size_t)z * SEQ * DMODEL;
    float* Vt = g_Vt + (size_t)z * DMODEL * SEQ;
    const int v0 = blockIdx.x * 32, t0 = blockIdx.y * 32;
    const int tx = threadIdx.x & 31, ty = threadIdx.x >> 5;
#pragma unroll
    for (int i = 0; i < 32; i += 8)
        tile[ty + i][tx] = V[(size_t)(t0 + ty + i) * DMODEL + v0 + tx];
    __syncthreads();
#pragma unroll
    for (int i = 0; i < 32; i += 8)
        Vt[(size_t)(v0 + ty + i) * SEQ + t0 + tx] = tile[tx][ty + i];
}

// ---------------------------------------------------------------------------
// row softmax in place (float4); zero-fills (q, wlen) for whole-tile PV reads
// ---------------------------------------------------------------------------
__global__ void __launch_bounds__(256) softmax_kernel() {
    __shared__ float sh[8];
    __shared__ float bcast;
    const int q = blockIdx.x, z = blockIdx.y, t = threadIdx.x;
    float* Srow = g_S + ((size_t)z * SEQ + q) * SEQ;
    const int len  = q + 1;
    const int wlen = ((q >> 7) + 1) << 7;          // 128-multiple >= len
    const int nIt  = (wlen + 1023) >> 10;          // float4 slabs of 1024

    float4 v4[2];
    float m = -INFINITY;
#pragma unroll 2
    for (int j = 0; j < nIt; j++) {
        int base = (t + j * 256) * 4;
        float4 x = make_float4(-INFINITY, -INFINITY, -INFINITY, -INFINITY);
        if (base < wlen) {
            x = *(const float4*)(Srow + base);
            if (base + 0 >= len) x.x = -INFINITY;
            if (base + 1 >= len) x.y = -INFINITY;
            if (base + 2 >= len) x.z = -INFINITY;
            if (base + 3 >= len) x.w = -INFINITY;
        }
        v4[j] = x;
        m = fmaxf(m, fmaxf(fmaxf(x.x, x.y), fmaxf(x.z, x.w)));
    }
#pragma unroll
    for (int o = 16; o; o >>= 1) m = fmaxf(m, __shfl_xor_sync(~0u, m, o));
    if ((t & 31) == 0) sh[t >> 5] = m;
    __syncthreads();
    if (t == 0) {
        float mm = sh[0];
        for (int w = 1; w < 8; w++) mm = fmaxf(mm, sh[w]);
        bcast = mm;
    }
    __syncthreads();
    m = bcast;

    float s = 0.f;
#pragma unroll 2
    for (int j = 0; j < nIt; j++) {
        float4 x = v4[j];
        x.x = __expf(x.x - m); x.y = __expf(x.y - m);
        x.z = __expf(x.z - m); x.w = __expf(x.w - m);
        v4[j] = x;
        s += (x.x + x.y) + (x.z + x.w);
    }
#pragma unroll
    for (int o = 16; o; o >>= 1) s += __shfl_xor_sync(~0u, s, o);
    __syncthreads();
    if ((t & 31) == 0) sh[t >> 5] = s;
    __syncthreads();
    if (t == 0) {
        float ss = 0.f;
        for (int w = 0; w < 8; w++) ss += sh[w];
        bcast = 1.f / ss;
    }
    __syncthreads();
    const float inv = bcast;
#pragma unroll 2
    for (int j = 0; j < nIt; j++) {
        int base = (t + j * 256) * 4;
        if (base < wlen) {
            float4 x = v4[j];
            *(float4*)(Srow + base) =
                make_float4(x.x * inv, x.y * inv, x.z * inv, x.w * inv);
        }
    }
}

__global__ void __launch_bounds__(256) copy_x_kernel(const float* __restrict__ x,
                                                     float* __restrict__ out) {
    int idx = blockIdx.x * 256 + threadIdx.x;
    int row = idx >> 7, c = (idx & 127) * 4;
    *(float4*)(out + (size_t)row * 1024 + c) =
        *(const float4*)(x + (size_t)row * 512 + c);
}

extern "C" void kernel_launch(void* const* d_in, const int* in_sizes, int n_in,
                              void* d_out, int out_size) {
    const float* x  = (const float*)d_in[0];
    const float* Wq = (const float*)d_in[1];
    const float* bq = (const float*)d_in[2];
    const float* Wk = (const float*)d_in[3];
    const float* bk = (const float*)d_in[4];
    const float* Wv = (const float*)d_in[5];
    const float* bv = (const float*)d_in[6];
    float* out = (float*)d_out;

    cudaFuncSetAttribute(qkv_gemm_tc, cudaFuncAttributeMaxDynamicSharedMemorySize, SMEM_BYTES);
    cudaFuncSetAttribute(s_gemm_tc,   cudaFuncAttributeMaxDynamicSharedMemorySize, SMEM_BYTES);
    cudaFuncSetAttribute(pv_gemm_tc,  cudaFuncAttributeMaxDynamicSharedMemorySize, SMEM_BYTES);

    copy_x_kernel<<<ROWS * (DMODEL / 4) / 256, 256>>>(x, out);
    wt_kernel<<<dim3(16, 16, 3), 256>>>(Wq, Wk, Wv);
    qkv_gemm_tc<<<dim3(4, 128, 3), 256, SMEM_BYTES>>>(x, bq, bk, bv);
    vt_kernel<<<dim3(16, 64, 8), 256>>>();
    s_gemm_tc<<<dim3(16, 16, 8), 256, SMEM_BYTES>>>();
    softmax_kernel<<<dim3(SEQ, BATCH), 256>>>();
    pv_gemm_tc<<<dim3(4, 16, 8), 256, SMEM_BYTES>>>(out);
}

// round 11
// speedup vs baseline: 1.3088x; 1.3088x over previous
#include <cuda_runtime.h>
#include <cstdint>
#include <math.h>

#define BATCH   8
#define SEQ     2048
#define DMODEL  512
#define ROWS    (BATCH * SEQ)
#define SCALE   0.044194173824159216f

__device__ float g_Q[(size_t)ROWS * DMODEL];
__device__ float g_K[(size_t)ROWS * DMODEL];
__device__ float g_V[(size_t)ROWS * DMODEL];
__device__ float g_S[(size_t)BATCH * SEQ * SEQ];

__device__ __forceinline__ float tf32r(float x) {
    uint32_t u;
    asm("cvt.rna.tf32.f32 %0, %1;" : "=r"(u) : "f"(x));
    return __uint_as_float(u);
}
__device__ __forceinline__ void mma8(float c[4], const uint32_t a[4],
                                     uint32_t b0, uint32_t b1) {
    asm volatile(
        "mma.sync.aligned.m16n8k8.row.col.f32.tf32.tf32.f32 "
        "{%0,%1,%2,%3}, {%4,%5,%6,%7}, {%8,%9}, {%0,%1,%2,%3};"
        : "+f"(c[0]), "+f"(c[1]), "+f"(c[2]), "+f"(c[3])
        : "r"(a[0]), "r"(a[1]), "r"(a[2]), "r"(a[3]), "r"(b0), "r"(b1));
}

#define TSTRIDE 36
#define TILE_FLOATS (128 * TSTRIDE)
#define SMEM_BYTES  (4 * TILE_FLOATS * 4)   // 73728 B

// gmem [row][col], col contiguous -> regs (tile rows r0.., k chunk c0..)
__device__ __forceinline__ void ldgTile(const float* G, int ld, int r0, int c0,
                                        float4 r[4]) {
    const int t = threadIdx.x, row = t >> 3, c4 = (t & 7) * 4;
#pragma unroll
    for (int i = 0; i < 4; i++)
        r[i] = *(const float4*)(G + (size_t)(r0 + row + i * 32) * ld + c0 + c4);
}
__device__ __forceinline__ void stsTile(float* S, const float4 r[4]) {
    const int t = threadIdx.x, row = t >> 3, c4 = (t & 7) * 4;
#pragma unroll
    for (int i = 0; i < 4; i++) {
        float4 v = make_float4(tf32r(r[i].x), tf32r(r[i].y),
                               tf32r(r[i].z), tf32r(r[i].w));
        *(float4*)&S[(row + i * 32) * TSTRIDE + c4] = v;
    }
}
// gmem [k][n], n contiguous -> transposed into smem [n][k]
__device__ __forceinline__ void ldgTileT(const float* G, int ld, int k0, int n0,
                                         float r[4][4]) {
    const int t = threadIdx.x, n = t & 127, kb = t >> 7;
#pragma unroll
    for (int it = 0; it < 4; it++) {
        int kr = k0 + (kb + it * 2) * 4;
#pragma unroll
        for (int j = 0; j < 4; j++)
            r[it][j] = G[(size_t)(kr + j) * ld + n0 + n];
    }
}
__device__ __forceinline__ void stsTileT(float* S, const float r[4][4]) {
    const int t = threadIdx.x, n = t & 127, kb = t >> 7;
#pragma unroll
    for (int it = 0; it < 4; it++) {
        float4 v = make_float4(tf32r(r[it][0]), tf32r(r[it][1]),
                               tf32r(r[it][2]), tf32r(r[it][3]));
        *(float4*)&S[n * TSTRIDE + (kb + it * 2) * 4] = v;
    }
}

// C[128,128] = A[128,32*kc] * B^T; 8 warps (4Mx2N), warp tile 32x64.
// Fragments via direct LDS (PTX m16n8k8 tf32 layout):
//   A: a0=(g,t) a1=(g+8,t) a2=(g,t+4) a3=(g+8,t+4)
//   B: b0=(k=t,n=g) b1=(k=t+4,n=g)          [g=lane>>2, t=lane&3]
// stride 36 (== 4 mod 32): lane L -> bank (L/4)*4+L%4, conflict-free.
template <bool BT>
__device__ __forceinline__ void gemm_core(float* sm,
                                          const float* A, int lda, int m0,
                                          const float* B, int ldb, int n0,
                                          int kChunks, float acc[2][8][4]) {
    float* As = sm;
    float* Bs = sm + 2 * TILE_FLOATS;
    const int lane = threadIdx.x & 31, wid = threadIdx.x >> 5;
    const int wm = wid >> 1, wn = wid & 1;
    const int g = lane >> 2, tt = lane & 3;

#pragma unroll
    for (int i = 0; i < 2; i++)
#pragma unroll
        for (int j = 0; j < 8; j++)
#pragma unroll
            for (int k = 0; k < 4; k++) acc[i][j][k] = 0.f;

    float4 ra[4]; float rbt[4][4]; float4 rbs[4];
    ldgTile(A, lda, m0, 0, ra);
    if (BT) ldgTileT(B, ldb, 0, n0, rbt); else ldgTile(B, ldb, n0, 0, rbs);
    stsTile(As, ra);
    if (BT) stsTileT(Bs, rbt); else stsTile(Bs, rbs);
    __syncthreads();

    for (int c = 0; c < kChunks; c++) {
        if (c + 1 < kChunks) {
            ldgTile(A, lda, m0, (c + 1) * 32, ra);
            if (BT) ldgTileT(B, ldb, (c + 1) * 32, n0, rbt);
            else    ldgTile(B, ldb, n0, (c + 1) * 32, rbs);
        }
        const float* Ab = As + (c & 1) * TILE_FLOATS + (wm * 32 + g) * TSTRIDE + tt;
        const float* Bb = Bs + (c & 1) * TILE_FLOATS + (wn * 64 + g) * TSTRIDE + tt;
#pragma unroll
        for (int ks = 0; ks < 4; ks++) {
            uint32_t a[2][4];
#pragma unroll
            for (int mi = 0; mi < 2; mi++) {
                const float* p = Ab + mi * (16 * TSTRIDE) + ks * 8;
                a[mi][0] = __float_as_uint(p[0]);
                a[mi][1] = __float_as_uint(p[8 * TSTRIDE]);
                a[mi][2] = __float_as_uint(p[4]);
                a[mi][3] = __float_as_uint(p[8 * TSTRIDE + 4]);
            }
#pragma unroll
            for (int nj = 0; nj < 8; nj++) {
                const float* p = Bb + nj * (8 * TSTRIDE) + ks * 8;
                uint32_t b0 = __float_as_uint(p[0]);
                uint32_t b1 = __float_as_uint(p[4]);
#pragma unroll
                for (int mi = 0; mi < 2; mi++)
                    mma8(acc[mi][nj], a[mi], b0, b1);
            }
        }
        if (c + 1 < kChunks) {
            __syncthreads();
            stsTile(As + ((c + 1) & 1) * TILE_FLOATS, ra);
            if (BT) stsTileT(Bs + ((c + 1) & 1) * TILE_FLOATS, rbt);
            else    stsTile (Bs + ((c + 1) & 1) * TILE_FLOATS, rbs);
            __syncthreads();
        }
    }
}
// acc coords: row = m0+wm*32+mi*16+(lane>>2) [+8 for c2/c3],
//             col = n0+wn*64+ni*8+(lane&3)*2, (c0,c1) adjacent cols.

__global__ void __launch_bounds__(256) qkv_gemm_tc(
    const float* __restrict__ x,
    const float* __restrict__ W0, const float* __restrict__ b0,
    const float* __restrict__ W1, const float* __restrict__ b1,
    const float* __restrict__ W2, const float* __restrict__ b2) {
    extern __shared__ float sm[];
    const float* W; const float* bias; float* C;
    if (blockIdx.z == 0)      { W = W0; bias = b0; C = g_Q; }
    else if (blockIdx.z == 1) { W = W1; bias = b1; C = g_K; }
    else                      { W = W2; bias = b2; C = g_V; }
    const int m0 = blockIdx.y * 128, n0 = blockIdx.x * 128;
    float acc[2][8][4];
    gemm_core<true>(sm, x, DMODEL, m0, W, DMODEL, n0, DMODEL / 32, acc);

    const int lane = threadIdx.x & 31, wid = threadIdx.x >> 5;
    const int wm = wid >> 1, wn = wid & 1;
    const int r = lane >> 2, cb = (lane & 3) * 2;
#pragma unroll
    for (int mi = 0; mi < 2; mi++)
#pragma unroll
        for (int ni = 0; ni < 8; ni++) {
            int row = m0 + wm * 32 + mi * 16 + r;
            int col = n0 + wn * 64 + ni * 8 + cb;
            float2 bb = *(const float2*)&bias[col];
            *(float2*)(C + (size_t)row * DMODEL + col) =
                make_float2(acc[mi][ni][0] + bb.x, acc[mi][ni][1] + bb.y);
            *(float2*)(C + (size_t)(row + 8) * DMODEL + col) =
                make_float2(acc[mi][ni][2] + bb.x, acc[mi][ni][3] + bb.y);
        }
}

__global__ void __launch_bounds__(256) s_gemm_tc() {
    if (blockIdx.x > blockIdx.y) return;   // strictly-future tile: skip
    extern __shared__ float sm[];
    const int z = blockIdx.z;
    const int m0 = blockIdx.y * 128, n0 = blockIdx.x * 128;
    const float* Q = g_Q + (size_t)z * SEQ * DMODEL;
    const float* K = g_K + (size_t)z * SEQ * DMODEL;
    float* S = g_S + (size_t)z * SEQ * SEQ;
    float acc[2][8][4];
    gemm_core<false>(sm, Q, DMODEL, m0, K, DMODEL, n0, DMODEL / 32, acc);

    const int lane = threadIdx.x & 31, wid = threadIdx.x >> 5;
    const int wm = wid >> 1, wn = wid & 1;
    const int r = lane >> 2, cb = (lane & 3) * 2;
#pragma unroll
    for (int mi = 0; mi < 2; mi++)
#pragma unroll
        for (int ni = 0; ni < 8; ni++) {
            int row = m0 + wm * 32 + mi * 16 + r;
            int col = n0 + wn * 64 + ni * 8 + cb;
            *(float2*)(S + (size_t)row * SEQ + col) =
                make_float2(acc[mi][ni][0] * SCALE, acc[mi][ni][1] * SCALE);
            *(float2*)(S + (size_t)(row + 8) * SEQ + col) =
                make_float2(acc[mi][ni][2] * SCALE, acc[mi][ni][3] * SCALE);
        }
}

__global__ void __launch_bounds__(256) pv_gemm_tc(float* __restrict__ out) {
    extern __shared__ float sm[];
    const int z = blockIdx.z, qt = blockIdx.y;
    const int m0 = qt * 128, n0 = blockIdx.x * 128;
    const float* P = g_S + (size_t)z * SEQ * SEQ;
    const float* V = g_V + (size_t)z * SEQ * DMODEL;
    float acc[2][8][4];
    gemm_core<true>(sm, P, SEQ, m0, V, DMODEL, n0, (qt + 1) * 4, acc);

    const int lane = threadIdx.x & 31, wid = threadIdx.x >> 5;
    const int wm = wid >> 1, wn = wid & 1;
    const int r = lane >> 2, cb = (lane & 3) * 2;
#pragma unroll
    for (int mi = 0; mi < 2; mi++)
#pragma unroll
        for (int ni = 0; ni < 8; ni++) {
            int row = m0 + wm * 32 + mi * 16 + r;
            int col = n0 + wn * 64 + ni * 8 + cb;
            *(float2*)(out + ((size_t)z * SEQ + row) * 1024 + 512 + col) =
                make_float2(acc[mi][ni][0], acc[mi][ni][1]);
            *(float2*)(out + ((size_t)z * SEQ + row + 8) * 1024 + 512 + col) =
                make_float2(acc[mi][ni][2], acc[mi][ni][3]);
        }
}

// row softmax in place (float4); zero-fills (q, wlen) for whole-tile PV reads
__global__ void __launch_bounds__(256) softmax_kernel() {
    __shared__ float sh[8];
    __shared__ float bcast;
    const int q = blockIdx.x, z = blockIdx.y, t = threadIdx.x;
    float* Srow = g_S + ((size_t)z * SEQ + q) * SEQ;
    const int len  = q + 1;
    const int wlen = ((q >> 7) + 1) << 7;
    const int nIt  = (wlen + 1023) >> 10;

    float4 v4[2];
    float m = -INFINITY;
#pragma unroll 2
    for (int j = 0; j < nIt; j++) {
        int base = (t + j * 256) * 4;
        float4 x = make_float4(-INFINITY, -INFINITY, -INFINITY, -INFINITY);
        if (base < wlen) {
            x = *(const float4*)(Srow + base);
            if (base + 0 >= len) x.x = -INFINITY;
            if (base + 1 >= len) x.y = -INFINITY;
            if (base + 2 >= len) x.z = -INFINITY;
            if (base + 3 >= len) x.w = -INFINITY;
        }
        v4[j] = x;
        m = fmaxf(m, fmaxf(fmaxf(x.x, x.y), fmaxf(x.z, x.w)));
    }
#pragma unroll
    for (int o = 16; o; o >>= 1) m = fmaxf(m, __shfl_xor_sync(~0u, m, o));
    if ((t & 31) == 0) sh[t >> 5] = m;
    __syncthreads();
    if (t == 0) {
        float mm = sh[0];
        for (int w = 1; w < 8; w++) mm = fmaxf(mm, sh[w]);
        bcast = mm;
    }
    __syncthreads();
    m = bcast;

    float s = 0.f;
#pragma unroll 2
    for (int j = 0; j < nIt; j++) {
        float4 x = v4[j];
        x.x = __expf(x.x - m); x.y = __expf(x.y - m);
        x.z = __expf(x.z - m); x.w = __expf(x.w - m);
        v4[j] = x;
        s += (x.x + x.y) + (x.z + x.w);
    }
#pragma unroll
    for (int o = 16; o; o >>= 1) s += __shfl_xor_sync(~0u, s, o);
    __syncthreads();
    if ((t & 31) == 0) sh[t >> 5] = s;
    __syncthreads();
    if (t == 0) {
        float ss = 0.f;
        for (int w = 0; w < 8; w++) ss += sh[w];
        bcast = 1.f / ss;
    }
    __syncthreads();
    const float inv = bcast;
#pragma unroll 2
    for (int j = 0; j < nIt; j++) {
        int base = (t + j * 256) * 4;
        if (base < wlen) {
            float4 x = v4[j];
            *(float4*)(Srow + base) =
                make_float4(x.x * inv, x.y * inv, x.z * inv, x.w * inv);
        }
    }
}

__global__ void __launch_bounds__(256) copy_x_kernel(const float* __restrict__ x,
                                                     float* __restrict__ out) {
    int idx = blockIdx.x * 256 + threadIdx.x;
    int row = idx >> 7, c = (idx & 127) * 4;
    *(float4*)(out + (size_t)row * 1024 + c) =
        *(const float4*)(x + (size_t)row * 512 + c);
}

extern "C" void kernel_launch(void* const* d_in, const int* in_sizes, int n_in,
                              void* d_out, int out_size) {
    const float* x  = (const float*)d_in[0];
    const float* Wq = (const float*)d_in[1];
    const float* bq = (const float*)d_in[2];
    const float* Wk = (const float*)d_in[3];
    const float* bk = (const float*)d_in[4];
    const float* Wv = (const float*)d_in[5];
    const float* bv = (const float*)d_in[6];
    float* out = (float*)d_out;

    cudaFuncSetAttribute(qkv_gemm_tc, cudaFuncAttributeMaxDynamicSharedMemorySize, SMEM_BYTES);
    cudaFuncSetAttribute(s_gemm_tc,   cudaFuncAttributeMaxDynamicSharedMemorySize, SMEM_BYTES);
    cudaFuncSetAttribute(pv_gemm_tc,  cudaFuncAttributeMaxDynamicSharedMemorySize, SMEM_BYTES);

    copy_x_kernel<<<ROWS * (DMODEL / 4) / 256, 256>>>(x, out);
    qkv_gemm_tc<<<dim3(4, 128, 3), 256, SMEM_BYTES>>>(x, Wq, bq, Wk, bk, Wv, bv);
    s_gemm_tc<<<dim3(16, 16, 8), 256, SMEM_BYTES>>>();
    softmax_kernel<<<dim3(SEQ, BATCH), 256>>>();
    pv_gemm_tc<<<dim3(4, 16, 8), 256, SMEM_BYTES>>>(out);
}

// round 12
// speedup vs baseline: 1.6274x; 1.2434x over previous
#include <cuda_runtime.h>
#include <cuda_fp16.h>
#include <cstdint>
#include <math.h>

#define BATCH   8
#define SEQ     2048
#define DMODEL  512
#define ROWS    (BATCH * SEQ)
#define SCALE   0.044194173824159216f

__device__ half  g_Q[(size_t)ROWS * DMODEL];
__device__ half  g_K[(size_t)ROWS * DMODEL];
__device__ half  g_V[(size_t)ROWS * DMODEL];
__device__ float g_S[(size_t)BATCH * SEQ * SEQ];
__device__ half  g_P[(size_t)BATCH * SEQ * SEQ];

// ---------------------------------------------------------------------------
// fp16 tensor-core mma: m16n8k16, fp32 accumulate.
// Fragment layout (PTX, g=lane>>2, t=lane&3):
//   a0={A[g][2t],A[g][2t+1]} a1={A[g+8][2t],..} a2={A[g][2t+8],..} a3={A[g+8][2t+8],..}
//   b0={B[2t][g],B[2t+1][g]} b1={B[2t+8][g],B[2t+9][g]}   (B^T[n][k] in smem)
//   c0,c1=row g cols 2t,2t+1; c2,c3=row g+8 same cols
// ---------------------------------------------------------------------------
__device__ __forceinline__ void mma16(float c[4], const uint32_t a[4],
                                      uint32_t b0, uint32_t b1) {
    asm volatile(
        "mma.sync.aligned.m16n8k16.row.col.f32.f16.f16.f32 "
        "{%0,%1,%2,%3}, {%4,%5,%6,%7}, {%8,%9}, {%0,%1,%2,%3};"
        : "+f"(c[0]), "+f"(c[1]), "+f"(c[2]), "+f"(c[3])
        : "r"(a[0]), "r"(a[1]), "r"(a[2]), "r"(a[3]), "r"(b0), "r"(b1));
}

// smem tile: 128 rows x 32 halves, row stride 40 halves (80B).
// Fragment LDS bank = (20*g + t) mod 32 -> full permutation, conflict-free.
#define HSTRIDE 40
#define TILE_H  (128 * HSTRIDE)           // 5120 halves = 10240 B
#define SMEM_BYTES (4 * TILE_H * 2)       // A0,A1,B0,B1 = 40960 B

// ---- loaders (all: 256 threads cover one 128x32 tile) ----
// straight fp32 -> fp16
__device__ __forceinline__ void ldg_f32S(const float* G, int ld, int r0, int c0,
                                         float4 v[4]) {
    const int t = threadIdx.x, row = t >> 1, kh = (t & 1) * 16;
    const float* s = G + (size_t)(r0 + row) * ld + c0 + kh;
#pragma unroll
    for (int i = 0; i < 4; i++) v[i] = *(const float4*)(s + i * 4);
}
__device__ __forceinline__ void sts_f32S(half* S, const float4 v[4]) {
    const int t = threadIdx.x, row = t >> 1, kh = (t & 1) * 16;
    union { half2 h2[8]; uint4 u[2]; } pk;
#pragma unroll
    for (int i = 0; i < 4; i++) {
        pk.h2[i * 2 + 0] = __floats2half2_rn(v[i].x, v[i].y);
        pk.h2[i * 2 + 1] = __floats2half2_rn(v[i].z, v[i].w);
    }
    uint4* d = (uint4*)&S[row * HSTRIDE + kh];
    d[0] = pk.u[0]; d[1] = pk.u[1];
}
// straight fp16 copy
__device__ __forceinline__ void ldg_h16S(const half* G, int ld, int r0, int c0,
                                         uint4 v[2]) {
    const int t = threadIdx.x, row = t >> 1, kh = (t & 1) * 16;
    const half* s = G + (size_t)(r0 + row) * ld + c0 + kh;
    v[0] = *(const uint4*)s;
    v[1] = *(const uint4*)(s + 8);
}
__device__ __forceinline__ void sts_h16S(half* S, const uint4 v[2]) {
    const int t = threadIdx.x, row = t >> 1, kh = (t & 1) * 16;
    uint4* d = (uint4*)&S[row * HSTRIDE + kh];
    d[0] = v[0]; d[1] = v[1];
}
// transposed fp32 [k][n] -> smem [n][k], fp16
__device__ __forceinline__ void ldg_f32T(const float* G, int ld, int k0, int n0,
                                         float v[16]) {
    const int t = threadIdx.x, n = t & 127, kb = t >> 7;
    const float* s = G + (size_t)(k0 + kb * 16) * ld + n0 + n;
#pragma unroll
    for (int j = 0; j < 16; j++) v[j] = s[(size_t)j * ld];
}
__device__ __forceinline__ void sts_f32T(half* S, const float v[16]) {
    const int t = threadIdx.x, n = t & 127, kb = t >> 7;
    union { half2 h2[8]; uint4 u[2]; } pk;
#pragma unroll
    for (int j = 0; j < 8; j++)
        pk.h2[j] = __floats2half2_rn(v[2 * j], v[2 * j + 1]);
    uint4* d = (uint4*)&S[n * HSTRIDE + kb * 16];
    d[0] = pk.u[0]; d[1] = pk.u[1];
}
// transposed fp16 [k][n] -> smem [n][k]
__device__ __forceinline__ void ldg_h16T(const half* G, int ld, int k0, int n0,
                                         half v[16]) {
    const int t = threadIdx.x, n = t & 127, kb = t >> 7;
    const half* s = G + (size_t)(k0 + kb * 16) * ld + n0 + n;
#pragma unroll
    for (int j = 0; j < 16; j++) v[j] = s[(size_t)j * ld];
}
__device__ __forceinline__ void sts_h16T(half* S, const half v[16]) {
    const int t = threadIdx.x, n = t & 127, kb = t >> 7;
    union { half h[16]; uint4 u[2]; } pk;
#pragma unroll
    for (int j = 0; j < 16; j++) pk.h[j] = v[j];
    uint4* d = (uint4*)&S[n * HSTRIDE + kb * 16];
    d[0] = pk.u[0]; d[1] = pk.u[1];
}

// ---------------------------------------------------------------------------
// C[128,128] = A[128,32*kc] * B^T; 8 warps (4Mx2N), warp tile 32x64.
// MODE 0: A fp32 straight, B fp32 transposed   (QKV)
// MODE 1: A fp16 straight, B fp16 straight     (S = Q K^T)
// MODE 2: A fp16 straight, B fp16 transposed   (PV)
// ---------------------------------------------------------------------------
template <int MODE>
__device__ __forceinline__ void gemm_core(half* sm,
                                          const void* Av, int lda, int m0,
                                          const void* Bv, int ldb, int n0,
                                          int kChunks, float acc[2][8][4]) {
    const float* Af = (const float*)Av; const half* Ah = (const half*)Av;
    const float* Bf = (const float*)Bv; const half* Bh = (const half*)Bv;
    half* As = sm;
    half* Bs = sm + 2 * TILE_H;
    const int lane = threadIdx.x & 31, wid = threadIdx.x >> 5;
    const int wm = wid >> 1, wn = wid & 1;
    const int g = lane >> 2, tt = lane & 3;

#pragma unroll
    for (int i = 0; i < 2; i++)
#pragma unroll
        for (int j = 0; j < 8; j++)
#pragma unroll
            for (int k = 0; k < 4; k++) acc[i][j][k] = 0.f;

    float4 raf[4]; uint4 rah[2];          // A prefetch
    float rbf[16]; uint4 rbh[2]; half rbt[16];   // B prefetch

#define LDGA(c) do { if (MODE == 0) ldg_f32S(Af, lda, m0, (c) * 32, raf); \
                     else           ldg_h16S(Ah, lda, m0, (c) * 32, rah); } while (0)
#define STSA(d) do { if (MODE == 0) sts_f32S(d, raf); else sts_h16S(d, rah); } while (0)
#define LDGB(c) do { if (MODE == 0)      ldg_f32T(Bf, ldb, (c) * 32, n0, rbf); \
                     else if (MODE == 1) ldg_h16S(Bh, ldb, n0, (c) * 32, rbh); \
                     else                ldg_h16T(Bh, ldb, (c) * 32, n0, rbt); } while (0)
#define STSB(d) do { if (MODE == 0)      sts_f32T(d, rbf); \
                     else if (MODE == 1) sts_h16S(d, rbh); \
                     else                sts_h16T(d, rbt); } while (0)

    LDGA(0); LDGB(0);
    STSA(As); STSB(Bs);
    __syncthreads();

    for (int c = 0; c < kChunks; c++) {
        if (c + 1 < kChunks) { LDGA(c + 1); LDGB(c + 1); }

        const half* Ab = As + (c & 1) * TILE_H + (wm * 32 + g) * HSTRIDE + 2 * tt;
        const half* Bb = Bs + (c & 1) * TILE_H + (wn * 64 + g) * HSTRIDE + 2 * tt;
#pragma unroll
        for (int ks = 0; ks < 2; ks++) {
            uint32_t a[2][4];
#pragma unroll
            for (int mi = 0; mi < 2; mi++) {
                const half* p = Ab + mi * (16 * HSTRIDE) + ks * 16;
                a[mi][0] = *(const uint32_t*)(p);
                a[mi][1] = *(const uint32_t*)(p + 8 * HSTRIDE);
                a[mi][2] = *(const uint32_t*)(p + 8);
                a[mi][3] = *(const uint32_t*)(p + 8 * HSTRIDE + 8);
            }
#pragma unroll
            for (int nj = 0; nj < 8; nj++) {
                const half* p = Bb + nj * (8 * HSTRIDE) + ks * 16;
                uint32_t b0 = *(const uint32_t*)(p);
                uint32_t b1 = *(const uint32_t*)(p + 8);
                mma16(acc[0][nj], a[0], b0, b1);
                mma16(acc[1][nj], a[1], b0, b1);
            }
        }
        if (c + 1 < kChunks) {
            __syncthreads();
            STSA(As + ((c + 1) & 1) * TILE_H);
            STSB(Bs + ((c + 1) & 1) * TILE_H);
            __syncthreads();
        }
    }
#undef LDGA
#undef STSA
#undef LDGB
#undef STSB
}
// acc coords: row = m0+wm*32+mi*16+(lane>>2) [+8 for c2/c3],
//             col = n0+wn*64+ni*8+(lane&3)*2, (c0,c1) adjacent cols.

// ---------------------------------------------------------------------------
__global__ void __launch_bounds__(256) qkv_gemm_tc(
    const float* __restrict__ x,
    const float* __restrict__ W0, const float* __restrict__ b0,
    const float* __restrict__ W1, const float* __restrict__ b1,
    const float* __restrict__ W2, const float* __restrict__ b2) {
    extern __shared__ half sm[];
    const float* W; const float* bias; half* C;
    if (blockIdx.z == 0)      { W = W0; bias = b0; C = g_Q; }
    else if (blockIdx.z == 1) { W = W1; bias = b1; C = g_K; }
    else                      { W = W2; bias = b2; C = g_V; }
    const int m0 = blockIdx.y * 128, n0 = blockIdx.x * 128;
    float acc[2][8][4];
    gemm_core<0>(sm, x, DMODEL, m0, W, DMODEL, n0, DMODEL / 32, acc);

    const int lane = threadIdx.x & 31, wid = threadIdx.x >> 5;
    const int wm = wid >> 1, wn = wid & 1;
    const int r = lane >> 2, cb = (lane & 3) * 2;
#pragma unroll
    for (int mi = 0; mi < 2; mi++)
#pragma unroll
        for (int ni = 0; ni < 8; ni++) {
            int row = m0 + wm * 32 + mi * 16 + r;
            int col = n0 + wn * 64 + ni * 8 + cb;
            float2 bb = *(const float2*)&bias[col];
            *(half2*)(C + (size_t)row * DMODEL + col) =
                __floats2half2_rn(acc[mi][ni][0] + bb.x, acc[mi][ni][1] + bb.y);
            *(half2*)(C + (size_t)(row + 8) * DMODEL + col) =
                __floats2half2_rn(acc[mi][ni][2] + bb.x, acc[mi][ni][3] + bb.y);
        }
}

__global__ void __launch_bounds__(256) s_gemm_tc() {
    if (blockIdx.x > blockIdx.y) return;   // strictly-future tile: skip
    extern __shared__ half sm[];
    const int z = blockIdx.z;
    const int m0 = blockIdx.y * 128, n0 = blockIdx.x * 128;
    const half* Q = g_Q + (size_t)z * SEQ * DMODEL;
    const half* K = g_K + (size_t)z * SEQ * DMODEL;
    float* S = g_S + (size_t)z * SEQ * SEQ;
    float acc[2][8][4];
    gemm_core<1>(sm, Q, DMODEL, m0, K, DMODEL, n0, DMODEL / 32, acc);

    const int lane = threadIdx.x & 31, wid = threadIdx.x >> 5;
    const int wm = wid >> 1, wn = wid & 1;
    const int r = lane >> 2, cb = (lane & 3) * 2;
#pragma unroll
    for (int mi = 0; mi < 2; mi++)
#pragma unroll
        for (int ni = 0; ni < 8; ni++) {
            int row = m0 + wm * 32 + mi * 16 + r;
            int col = n0 + wn * 64 + ni * 8 + cb;
            *(float2*)(S + (size_t)row * SEQ + col) =
                make_float2(acc[mi][ni][0] * SCALE, acc[mi][ni][1] * SCALE);
            *(float2*)(S + (size_t)(row + 8) * SEQ + col) =
                make_float2(acc[mi][ni][2] * SCALE, acc[mi][ni][3] * SCALE);
        }
}

__global__ void __launch_bounds__(256) pv_gemm_tc(float* __restrict__ out) {
    extern __shared__ half sm[];
    const int z = blockIdx.z, qt = blockIdx.y;
    const int m0 = qt * 128, n0 = blockIdx.x * 128;
    const half* P = g_P + (size_t)z * SEQ * SEQ;
    const half* V = g_V + (size_t)z * SEQ * DMODEL;
    float acc[2][8][4];
    gemm_core<2>(sm, P, SEQ, m0, V, DMODEL, n0, (qt + 1) * 4, acc);

    const int lane = threadIdx.x & 31, wid = threadIdx.x >> 5;
    const int wm = wid >> 1, wn = wid & 1;
    const int r = lane >> 2, cb = (lane & 3) * 2;
#pragma unroll
    for (int mi = 0; mi < 2; mi++)
#pragma unroll
        for (int ni = 0; ni < 8; ni++) {
            int row = m0 + wm * 32 + mi * 16 + r;
            int col = n0 + wn * 64 + ni * 8 + cb;
            *(float2*)(out + ((size_t)z * SEQ + row) * 1024 + 512 + col) =
                make_float2(acc[mi][ni][0], acc[mi][ni][1]);
            *(float2*)(out + ((size_t)z * SEQ + row + 8) * 1024 + 512 + col) =
                make_float2(acc[mi][ni][2], acc[mi][ni][3]);
        }
}

// row softmax: reads fp32 S, writes fp16 P; zero-fills (q, wlen)
__global__ void __launch_bounds__(256) softmax_kernel() {
    __shared__ float sh[8];
    __shared__ float bcast;
    const int q = blockIdx.x, z = blockIdx.y, t = threadIdx.x;
    const float* Srow = g_S + ((size_t)z * SEQ + q) * SEQ;
    half* Prow = g_P + ((size_t)z * SEQ + q) * SEQ;
    const int len  = q + 1;
    const int wlen = ((q >> 7) + 1) << 7;
    const int nIt  = (wlen + 1023) >> 10;

    float4 v4[2];
    float m = -INFINITY;
#pragma unroll 2
    for (int j = 0; j < nIt; j++) {
        int base = (t + j * 256) * 4;
        float4 x = make_float4(-INFINITY, -INFINITY, -INFINITY, -INFINITY);
        if (base < wlen) {
            x = *(const float4*)(Srow + base);
            if (base + 0 >= len) x.x = -INFINITY;
            if (base + 1 >= len) x.y = -INFINITY;
            if (base + 2 >= len) x.z = -INFINITY;
            if (base + 3 >= len) x.w = -INFINITY;
        }
        v4[j] = x;
        m = fmaxf(m, fmaxf(fmaxf(x.x, x.y), fmaxf(x.z, x.w)));
    }
#pragma unroll
    for (int o = 16; o; o >>= 1) m = fmaxf(m, __shfl_xor_sync(~0u, m, o));
    if ((t & 31) == 0) sh[t >> 5] = m;
    __syncthreads();
    if (t == 0) {
        float mm = sh[0];
        for (int w = 1; w < 8; w++) mm = fmaxf(mm, sh[w]);
        bcast = mm;
    }
    __syncthreads();
    m = bcast;

    float s = 0.f;
#pragma unroll 2
    for (int j = 0; j < nIt; j++) {
        float4 x = v4[j];
        x.x = __expf(x.x - m); x.y = __expf(x.y - m);
        x.z = __expf(x.z - m); x.w = __expf(x.w - m);
        v4[j] = x;
        s += (x.x + x.y) + (x.z + x.w);
    }
#pragma unroll
    for (int o = 16; o; o >>= 1) s += __shfl_xor_sync(~0u, s, o);
    __syncthreads();
    if ((t & 31) == 0) sh[t >> 5] = s;
    __syncthreads();
    if (t == 0) {
        float ss = 0.f;
        for (int w = 0; w < 8; w++) ss += sh[w];
        bcast = 1.f / ss;
    }
    __syncthreads();
    const float inv = bcast;
#pragma unroll 2
    for (int j = 0; j < nIt; j++) {
        int base = (t + j * 256) * 4;
        if (base < wlen) {
            float4 x = v4[j];
            union { half2 h2[2]; uint2 u; } o;
            o.h2[0] = __floats2half2_rn(x.x * inv, x.y * inv);
            o.h2[1] = __floats2half2_rn(x.z * inv, x.w * inv);
            *(uint2*)(Prow + base) = o.u;
        }
    }
}

__global__ void __launch_bounds__(256) copy_x_kernel(const float* __restrict__ x,
                                                     float* __restrict__ out) {
    int idx = blockIdx.x * 256 + threadIdx.x;
    int row = idx >> 7, c = (idx & 127) * 4;
    *(float4*)(out + (size_t)row * 1024 + c) =
        *(const float4*)(x + (size_t)row * 512 + c);
}

extern "C" void kernel_launch(void* const* d_in, const int* in_sizes, int n_in,
                              void* d_out, int out_size) {
    const float* x  = (const float*)d_in[0];
    const float* Wq = (const float*)d_in[1];
    const float* bq = (const float*)d_in[2];
    const float* Wk = (const float*)d_in[3];
    const float* bk = (const float*)d_in[4];
    const float* Wv = (const float*)d_in[5];
    const float* bv = (const float*)d_in[6];
    float* out = (float*)d_out;

    cudaFuncSetAttribute(qkv_gemm_tc, cudaFuncAttributeMaxDynamicSharedMemorySize, SMEM_BYTES);
    cudaFuncSetAttribute(s_gemm_tc,   cudaFuncAttributeMaxDynamicSharedMemorySize, SMEM_BYTES);
    cudaFuncSetAttribute(pv_gemm_tc,  cudaFuncAttributeMaxDynamicSharedMemorySize, SMEM_BYTES);

    copy_x_kernel<<<ROWS * (DMODEL / 4) / 256, 256>>>(x, out);
    qkv_gemm_tc<<<dim3(4, 128, 3), 256, SMEM_BYTES>>>(x, Wq, bq, Wk, bk, Wv, bv);
    s_gemm_tc<<<dim3(16, 16, 8), 256, SMEM_BYTES>>>();
    softmax_kernel<<<dim3(SEQ, BATCH), 256>>>();
    pv_gemm_tc<<<dim3(4, 16, 8), 256, SMEM_BYTES>>>(out);
}